// round 1
// baseline (speedup 1.0000x reference)
#include <cuda_runtime.h>

#define NUM_USERS 100000
#define NUM_ITEMS 50000
#define N_NODES   150000
#define DIM       64
#define NUM_EDGES 4000000

// Scratch ping-pong buffers (allocation-free rule: __device__ globals).
__device__ float g_bufA[N_NODES * DIM];
__device__ float g_bufB[N_NODES * DIM];

// -------------------------------------------------------------------------
// Kernel 1: acc(out) = emb, cur(bufA) = emb, next(bufB) = 0.  float4 lanes.
// -------------------------------------------------------------------------
__global__ void lgcn_init(const float* __restrict__ user_emb,
                          const float* __restrict__ item_emb,
                          float* __restrict__ out)
{
    const int total4 = N_NODES * DIM / 4;
    int i = blockIdx.x * blockDim.x + threadIdx.x;
    if (i >= total4) return;

    const int user4 = NUM_USERS * DIM / 4;
    float4 v;
    if (i < user4) v = ((const float4*)user_emb)[i];
    else           v = ((const float4*)item_emb)[i - user4];

    ((float4*)out)[i]    = v;
    ((float4*)g_bufA)[i] = v;
    ((float4*)g_bufB)[i] = make_float4(0.f, 0.f, 0.f, 0.f);
}

// -------------------------------------------------------------------------
// Kernel 2: SpMM scatter.  16 threads per edge, each owns 4 dims (float4).
// next[row] += val * cur[col].  atomicAdd return unused -> RED.E.ADD.F32.
// -------------------------------------------------------------------------
__global__ void lgcn_spmm(const float* __restrict__ edge_vals,
                          const int*   __restrict__ edge_row,
                          const int*   __restrict__ edge_col,
                          const float* __restrict__ cur,
                          float*       __restrict__ nxt)
{
    unsigned int gid = blockIdx.x * blockDim.x + threadIdx.x;
    unsigned int e   = gid >> 4;          // edge index
    unsigned int d   = (gid & 15u) << 2;  // dim offset (0,4,...,60)
    if (e >= NUM_EDGES) return;

    int   r = __ldg(edge_row + e);
    int   c = __ldg(edge_col + e);
    float v = __ldg(edge_vals + e);

    float4 x = *(const float4*)(cur + (size_t)c * DIM + d);

    float* dst = nxt + (size_t)r * DIM + d;
    atomicAdd(dst + 0, v * x.x);
    atomicAdd(dst + 1, v * x.y);
    atomicAdd(dst + 2, v * x.z);
    atomicAdd(dst + 3, v * x.w);
}

// -------------------------------------------------------------------------
// Kernel 3: acc += newly-computed layer; zero the other buffer so it can
// serve as the next layer's scatter target.
// -------------------------------------------------------------------------
__global__ void lgcn_accum(const float* __restrict__ newbuf,
                           float* __restrict__ zerobuf,
                           float* __restrict__ out)
{
    const int total4 = N_NODES * DIM / 4;
    int i = blockIdx.x * blockDim.x + threadIdx.x;
    if (i >= total4) return;

    float4 n = ((const float4*)newbuf)[i];
    float4 a = ((float4*)out)[i];
    a.x += n.x; a.y += n.y; a.z += n.z; a.w += n.w;
    ((float4*)out)[i] = a;
    ((float4*)zerobuf)[i] = make_float4(0.f, 0.f, 0.f, 0.f);
}

// -------------------------------------------------------------------------
// Kernel 4: final layer: out = (out + newbuf) * 0.25
// -------------------------------------------------------------------------
__global__ void lgcn_accum_final(const float* __restrict__ newbuf,
                                 float* __restrict__ out)
{
    const int total4 = N_NODES * DIM / 4;
    int i = blockIdx.x * blockDim.x + threadIdx.x;
    if (i >= total4) return;

    float4 n = ((const float4*)newbuf)[i];
    float4 a = ((float4*)out)[i];
    a.x = (a.x + n.x) * 0.25f;
    a.y = (a.y + n.y) * 0.25f;
    a.z = (a.z + n.z) * 0.25f;
    a.w = (a.w + n.w) * 0.25f;
    ((float4*)out)[i] = a;
}

// -------------------------------------------------------------------------
// Launch: fixed 8-kernel sequence, graph-capturable, no sync, no alloc.
// -------------------------------------------------------------------------
extern "C" void kernel_launch(void* const* d_in, const int* in_sizes, int n_in,
                              void* d_out, int out_size)
{
    const float* user_emb  = (const float*)d_in[0];
    const float* item_emb  = (const float*)d_in[1];
    const float* edge_vals = (const float*)d_in[2];
    const int*   edge_row  = (const int*)d_in[3];
    const int*   edge_col  = (const int*)d_in[4];
    float* out = (float*)d_out;

    float *bufA, *bufB;
    cudaGetSymbolAddress((void**)&bufA, g_bufA);
    cudaGetSymbolAddress((void**)&bufB, g_bufB);

    const int total4 = N_NODES * DIM / 4;               // 2.4M float4
    const int VEC_BLK = 256;
    const int vec_grid = (total4 + VEC_BLK - 1) / VEC_BLK;

    const unsigned int spmm_threads = NUM_EDGES * 16u;  // 64M
    const int SPMM_BLK = 256;
    const unsigned int spmm_grid = (spmm_threads + SPMM_BLK - 1) / SPMM_BLK;

    // init: out = emb, cur(A) = emb, next(B) = 0
    lgcn_init<<<vec_grid, VEC_BLK>>>(user_emb, item_emb, out);

    // layer 1: A -> B ; out += B ; zero A
    lgcn_spmm<<<spmm_grid, SPMM_BLK>>>(edge_vals, edge_row, edge_col, bufA, bufB);
    lgcn_accum<<<vec_grid, VEC_BLK>>>(bufB, bufA, out);

    // layer 2: B -> A ; out += A ; zero B
    lgcn_spmm<<<spmm_grid, SPMM_BLK>>>(edge_vals, edge_row, edge_col, bufB, bufA);
    lgcn_accum<<<vec_grid, VEC_BLK>>>(bufA, bufB, out);

    // layer 3: A -> B ; out = (out + B) * 0.25
    lgcn_spmm<<<spmm_grid, SPMM_BLK>>>(edge_vals, edge_row, edge_col, bufA, bufB);
    lgcn_accum_final<<<vec_grid, VEC_BLK>>>(bufB, out);
}

// round 2
// speedup vs baseline: 1.6903x; 1.6903x over previous
#include <cuda_runtime.h>

#define NUM_USERS 100000
#define NUM_ITEMS 50000
#define N_NODES   150000
#define DIM       64
#define NUM_EDGES 4000000

// Scratch ping-pong buffers (allocation-free rule: __device__ globals).
__device__ float g_bufA[N_NODES * DIM];
__device__ float g_bufB[N_NODES * DIM];

// Vectorized global reduction: one L2 atomic op covering 16 bytes.
__device__ __forceinline__ void red_add_v4(float* addr, float a, float b,
                                           float c, float d)
{
    asm volatile("red.global.add.v4.f32 [%0], {%1, %2, %3, %4};"
                 :: "l"(addr), "f"(a), "f"(b), "f"(c), "f"(d)
                 : "memory");
}

// -------------------------------------------------------------------------
// Kernel 1: acc(out) = emb, cur(bufA) = emb, next(bufB) = 0.  float4 lanes.
// -------------------------------------------------------------------------
__global__ void lgcn_init(const float* __restrict__ user_emb,
                          const float* __restrict__ item_emb,
                          float* __restrict__ out)
{
    const int total4 = N_NODES * DIM / 4;
    int i = blockIdx.x * blockDim.x + threadIdx.x;
    if (i >= total4) return;

    const int user4 = NUM_USERS * DIM / 4;
    float4 v;
    if (i < user4) v = ((const float4*)user_emb)[i];
    else           v = ((const float4*)item_emb)[i - user4];

    ((float4*)out)[i]    = v;
    ((float4*)g_bufA)[i] = v;
    ((float4*)g_bufB)[i] = make_float4(0.f, 0.f, 0.f, 0.f);
}

// -------------------------------------------------------------------------
// Kernel 2: SpMM scatter.  4 threads per edge; each thread owns 16 dims
// (4 x float4 gather, 4 x red.global.add.v4.f32 scatter).
// -------------------------------------------------------------------------
__global__ void __launch_bounds__(256)
lgcn_spmm(const float* __restrict__ edge_vals,
          const int*   __restrict__ edge_row,
          const int*   __restrict__ edge_col,
          const float* __restrict__ cur,
          float*       __restrict__ nxt)
{
    unsigned int gid = blockIdx.x * blockDim.x + threadIdx.x;
    unsigned int e   = gid >> 2;          // edge index
    unsigned int d0  = (gid & 3u) << 4;   // dim offset: 0,16,32,48
    if (e >= NUM_EDGES) return;

    int   r = __ldg(edge_row + e);
    int   c = __ldg(edge_col + e);
    float v = __ldg(edge_vals + e);

    const float4* src = (const float4*)(cur + (size_t)c * DIM + d0);
    float4 x0 = src[0];
    float4 x1 = src[1];
    float4 x2 = src[2];
    float4 x3 = src[3];

    float* dst = nxt + (size_t)r * DIM + d0;
    red_add_v4(dst + 0,  v * x0.x, v * x0.y, v * x0.z, v * x0.w);
    red_add_v4(dst + 4,  v * x1.x, v * x1.y, v * x1.z, v * x1.w);
    red_add_v4(dst + 8,  v * x2.x, v * x2.y, v * x2.z, v * x2.w);
    red_add_v4(dst + 12, v * x3.x, v * x3.y, v * x3.z, v * x3.w);
}

// -------------------------------------------------------------------------
// Kernel 3: acc += newly-computed layer; zero the other buffer so it can
// serve as the next layer's scatter target.
// -------------------------------------------------------------------------
__global__ void lgcn_accum(const float* __restrict__ newbuf,
                           float* __restrict__ zerobuf,
                           float* __restrict__ out)
{
    const int total4 = N_NODES * DIM / 4;
    int i = blockIdx.x * blockDim.x + threadIdx.x;
    if (i >= total4) return;

    float4 n = ((const float4*)newbuf)[i];
    float4 a = ((float4*)out)[i];
    a.x += n.x; a.y += n.y; a.z += n.z; a.w += n.w;
    ((float4*)out)[i] = a;
    ((float4*)zerobuf)[i] = make_float4(0.f, 0.f, 0.f, 0.f);
}

// -------------------------------------------------------------------------
// Kernel 4: final layer: out = (out + newbuf) * 0.25
// -------------------------------------------------------------------------
__global__ void lgcn_accum_final(const float* __restrict__ newbuf,
                                 float* __restrict__ out)
{
    const int total4 = N_NODES * DIM / 4;
    int i = blockIdx.x * blockDim.x + threadIdx.x;
    if (i >= total4) return;

    float4 n = ((const float4*)newbuf)[i];
    float4 a = ((float4*)out)[i];
    a.x = (a.x + n.x) * 0.25f;
    a.y = (a.y + n.y) * 0.25f;
    a.z = (a.z + n.z) * 0.25f;
    a.w = (a.w + n.w) * 0.25f;
    ((float4*)out)[i] = a;
}

// -------------------------------------------------------------------------
// Launch: fixed 8-kernel sequence, graph-capturable, no sync, no alloc.
// -------------------------------------------------------------------------
extern "C" void kernel_launch(void* const* d_in, const int* in_sizes, int n_in,
                              void* d_out, int out_size)
{
    const float* user_emb  = (const float*)d_in[0];
    const float* item_emb  = (const float*)d_in[1];
    const float* edge_vals = (const float*)d_in[2];
    const int*   edge_row  = (const int*)d_in[3];
    const int*   edge_col  = (const int*)d_in[4];
    float* out = (float*)d_out;

    float *bufA, *bufB;
    cudaGetSymbolAddress((void**)&bufA, g_bufA);
    cudaGetSymbolAddress((void**)&bufB, g_bufB);

    const int total4 = N_NODES * DIM / 4;               // 2.4M float4
    const int VEC_BLK = 256;
    const int vec_grid = (total4 + VEC_BLK - 1) / VEC_BLK;

    const unsigned int spmm_threads = NUM_EDGES * 4u;   // 16M
    const int SPMM_BLK = 256;
    const unsigned int spmm_grid = (spmm_threads + SPMM_BLK - 1) / SPMM_BLK;

    // init: out = emb, cur(A) = emb, next(B) = 0
    lgcn_init<<<vec_grid, VEC_BLK>>>(user_emb, item_emb, out);

    // layer 1: A -> B ; out += B ; zero A
    lgcn_spmm<<<spmm_grid, SPMM_BLK>>>(edge_vals, edge_row, edge_col, bufA, bufB);
    lgcn_accum<<<vec_grid, VEC_BLK>>>(bufB, bufA, out);

    // layer 2: B -> A ; out += A ; zero B
    lgcn_spmm<<<spmm_grid, SPMM_BLK>>>(edge_vals, edge_row, edge_col, bufB, bufA);
    lgcn_accum<<<vec_grid, VEC_BLK>>>(bufA, bufB, out);

    // layer 3: A -> B ; out = (out + B) * 0.25
    lgcn_spmm<<<spmm_grid, SPMM_BLK>>>(edge_vals, edge_row, edge_col, bufA, bufB);
    lgcn_accum_final<<<vec_grid, VEC_BLK>>>(bufB, out);
}

// round 3
// speedup vs baseline: 2.4940x; 1.4755x over previous
#include <cuda_runtime.h>

#define NUM_USERS 100000
#define NUM_ITEMS 50000
#define N_NODES   150000
#define DIM       64
#define NUM_EDGES 4000000

// Scratch (allocation-free rule: __device__ globals).
__device__ float g_bufA[N_NODES * DIM];
__device__ float g_bufB[N_NODES * DIM];
__device__ int   g_scol[NUM_EDGES];
__device__ float g_sval[NUM_EDGES];
__device__ int   g_hist[N_NODES];
__device__ int   g_rowptr[N_NODES + 1];
__device__ int   g_cursor[N_NODES];

// -------------------------------------------------------------------------
// Kernel 1: out = emb, cur(bufA) = emb; zero histogram.
// -------------------------------------------------------------------------
__global__ void lgcn_init(const float* __restrict__ user_emb,
                          const float* __restrict__ item_emb,
                          float* __restrict__ out)
{
    const int total4 = N_NODES * DIM / 4;
    int i = blockIdx.x * blockDim.x + threadIdx.x;
    if (i >= total4) return;

    const int user4 = NUM_USERS * DIM / 4;
    float4 v;
    if (i < user4) v = ((const float4*)user_emb)[i];
    else           v = ((const float4*)item_emb)[i - user4];

    ((float4*)out)[i]    = v;
    ((float4*)g_bufA)[i] = v;

    if (i < N_NODES) g_hist[i] = 0;
}

// -------------------------------------------------------------------------
// Kernel 2: degree histogram.
// -------------------------------------------------------------------------
__global__ void lgcn_hist(const int* __restrict__ edge_row)
{
    int e = blockIdx.x * blockDim.x + threadIdx.x;
    if (e >= NUM_EDGES) return;
    atomicAdd(&g_hist[edge_row[e]], 1);
}

// -------------------------------------------------------------------------
// Kernel 3: single-block exclusive scan -> row_ptr + cursor.
// -------------------------------------------------------------------------
__global__ void lgcn_scan()
{
    const int T = 1024;
    const int CHUNK = (N_NODES + T - 1) / T;   // 147
    __shared__ int s_part[T];

    int t   = threadIdx.x;
    int beg = t * CHUNK;
    int end = min(beg + CHUNK, N_NODES);

    int sum = 0;
    for (int i = beg; i < end; i++) sum += g_hist[i];
    s_part[t] = sum;
    __syncthreads();

    // Hillis-Steele inclusive scan over 1024 partials.
    for (int off = 1; off < T; off <<= 1) {
        int v = (t >= off) ? s_part[t - off] : 0;
        __syncthreads();
        s_part[t] += v;
        __syncthreads();
    }

    int run = s_part[t] - sum;   // exclusive prefix of this chunk
    for (int i = beg; i < end; i++) {
        g_rowptr[i] = run;
        g_cursor[i] = run;
        run += g_hist[i];
    }
    if (t == 0) g_rowptr[N_NODES] = NUM_EDGES;
}

// -------------------------------------------------------------------------
// Kernel 4: scatter edges into row-sorted arrays.
// -------------------------------------------------------------------------
__global__ void lgcn_scatter(const float* __restrict__ edge_vals,
                             const int*   __restrict__ edge_row,
                             const int*   __restrict__ edge_col)
{
    int e = blockIdx.x * blockDim.x + threadIdx.x;
    if (e >= NUM_EDGES) return;
    int r = edge_row[e];
    int pos = atomicAdd(&g_cursor[r], 1);
    g_scol[pos] = edge_col[e];
    g_sval[pos] = edge_vals[e];
}

// -------------------------------------------------------------------------
// Kernel 5: warp-per-node CSR gather, fused with accumulator update.
// out[node] = (out[node] + sum_e val*cur[col]) * scale;  nxt = layer result.
// -------------------------------------------------------------------------
__global__ void __launch_bounds__(256)
lgcn_gather(const float* __restrict__ cur,
            float*       __restrict__ nxt,
            float*       __restrict__ out,
            float scale, int write_nxt)
{
    int warp = (blockIdx.x * blockDim.x + threadIdx.x) >> 5;
    int lane = threadIdx.x & 31;
    if (warp >= N_NODES) return;

    int start = g_rowptr[warp];
    int end   = g_rowptr[warp + 1];

    float2 acc = make_float2(0.f, 0.f);

    for (int base = start; base < end; base += 32) {
        int idx = base + lane;
        int   c = 0;
        float v = 0.f;
        if (idx < end) { c = g_scol[idx]; v = g_sval[idx]; }
        int n = min(32, end - base);
        #pragma unroll 4
        for (int j = 0; j < n; j++) {
            int   cj = __shfl_sync(0xffffffffu, c, j);
            float vj = __shfl_sync(0xffffffffu, v, j);
            float2 x = ((const float2*)(cur + (size_t)cj * DIM))[lane];
            acc.x += vj * x.x;
            acc.y += vj * x.y;
        }
    }

    float2* o = (float2*)(out + (size_t)warp * DIM);
    float2 a = o[lane];
    a.x = (a.x + acc.x) * scale;
    a.y = (a.y + acc.y) * scale;
    o[lane] = a;

    if (write_nxt)
        ((float2*)(nxt + (size_t)warp * DIM))[lane] = acc;
}

// -------------------------------------------------------------------------
// Launch: 7 kernels, graph-capturable, no sync, no alloc.
// -------------------------------------------------------------------------
extern "C" void kernel_launch(void* const* d_in, const int* in_sizes, int n_in,
                              void* d_out, int out_size)
{
    const float* user_emb  = (const float*)d_in[0];
    const float* item_emb  = (const float*)d_in[1];
    const float* edge_vals = (const float*)d_in[2];
    const int*   edge_row  = (const int*)d_in[3];
    const int*   edge_col  = (const int*)d_in[4];
    float* out = (float*)d_out;

    float *bufA, *bufB;
    cudaGetSymbolAddress((void**)&bufA, g_bufA);
    cudaGetSymbolAddress((void**)&bufB, g_bufB);

    const int total4 = N_NODES * DIM / 4;
    const int vec_grid = (total4 + 255) / 256;

    const int edge_grid = (NUM_EDGES + 255) / 256;

    const int warps_per_block = 256 / 32;
    const int gather_grid = (N_NODES + warps_per_block - 1) / warps_per_block;

    // Build CSR (re-done every replay: deterministic, no call-count state).
    lgcn_init<<<vec_grid, 256>>>(user_emb, item_emb, out);
    lgcn_hist<<<edge_grid, 256>>>(edge_row);
    lgcn_scan<<<1, 1024>>>();
    lgcn_scatter<<<edge_grid, 256>>>(edge_vals, edge_row, edge_col);

    // 3 propagation layers, accumulation fused.
    lgcn_gather<<<gather_grid, 256>>>(bufA, bufB, out, 1.0f,   1);
    lgcn_gather<<<gather_grid, 256>>>(bufB, bufA, out, 1.0f,   1);
    lgcn_gather<<<gather_grid, 256>>>(bufA, bufB, out, 0.25f,  0);
}

// round 4
// speedup vs baseline: 2.7082x; 1.0859x over previous
#include <cuda_runtime.h>

#define NUM_USERS 100000
#define NUM_ITEMS 50000
#define N_NODES   150000
#define DIM       64
#define NUM_EDGES 4000000

// Scratch (allocation-free rule: __device__ globals).
__device__ float g_bufA[N_NODES * DIM];
__device__ float g_bufB[N_NODES * DIM];
__device__ int2  g_edges[NUM_EDGES];       // interleaved {col, val-bits}
__device__ int   g_hist[N_NODES];
__device__ int   g_rowptr[N_NODES + 1];
__device__ int   g_cursor[N_NODES];

// -------------------------------------------------------------------------
// Kernel 1: zero histogram (only fixed-cost init left).
// -------------------------------------------------------------------------
__global__ void lgcn_zero_hist()
{
    int i = blockIdx.x * blockDim.x + threadIdx.x;
    if (i < N_NODES) g_hist[i] = 0;
}

// -------------------------------------------------------------------------
// Kernel 2: degree histogram, 4 edges/thread (int4 loads).
// -------------------------------------------------------------------------
__global__ void lgcn_hist(const int* __restrict__ edge_row)
{
    int i = blockIdx.x * blockDim.x + threadIdx.x;
    if (i >= NUM_EDGES / 4) return;
    int4 r = ((const int4*)edge_row)[i];
    atomicAdd(&g_hist[r.x], 1);
    atomicAdd(&g_hist[r.y], 1);
    atomicAdd(&g_hist[r.z], 1);
    atomicAdd(&g_hist[r.w], 1);
}

// -------------------------------------------------------------------------
// Kernel 3: single-block exclusive scan -> row_ptr + cursor.
// -------------------------------------------------------------------------
__global__ void lgcn_scan()
{
    const int T = 1024;
    const int CHUNK = (N_NODES + T - 1) / T;   // 147
    __shared__ int s_part[T];

    int t   = threadIdx.x;
    int beg = t * CHUNK;
    int end = min(beg + CHUNK, N_NODES);

    int sum = 0;
    for (int i = beg; i < end; i++) sum += g_hist[i];
    s_part[t] = sum;
    __syncthreads();

    for (int off = 1; off < T; off <<= 1) {
        int v = (t >= off) ? s_part[t - off] : 0;
        __syncthreads();
        s_part[t] += v;
        __syncthreads();
    }

    int run = s_part[t] - sum;
    for (int i = beg; i < end; i++) {
        g_rowptr[i] = run;
        g_cursor[i] = run;
        run += g_hist[i];
    }
    if (t == 0) g_rowptr[N_NODES] = NUM_EDGES;
}

// -------------------------------------------------------------------------
// Kernel 4: scatter edges into row-sorted interleaved array, 4 edges/thread.
// -------------------------------------------------------------------------
__global__ void lgcn_scatter(const float* __restrict__ edge_vals,
                             const int*   __restrict__ edge_row,
                             const int*   __restrict__ edge_col)
{
    int i = blockIdx.x * blockDim.x + threadIdx.x;
    if (i >= NUM_EDGES / 4) return;
    int4   r = ((const int4*)edge_row)[i];
    int4   c = ((const int4*)edge_col)[i];
    float4 v = ((const float4*)edge_vals)[i];

    int p;
    p = atomicAdd(&g_cursor[r.x], 1); g_edges[p] = make_int2(c.x, __float_as_int(v.x));
    p = atomicAdd(&g_cursor[r.y], 1); g_edges[p] = make_int2(c.y, __float_as_int(v.y));
    p = atomicAdd(&g_cursor[r.z], 1); g_edges[p] = make_int2(c.z, __float_as_int(v.z));
    p = atomicAdd(&g_cursor[r.w], 1); g_edges[p] = make_int2(c.w, __float_as_int(v.w));
}

// -------------------------------------------------------------------------
// Kernel 5: warp-per-node CSR gather.  Edge meta staged in smem (LDS.64
// broadcast, no shfl chains).  MODE 0: layer1 (virtual concat input,
// out = emb + acc).  MODE 1: out += acc.  MODE 2: out = (out+acc)*0.25.
// -------------------------------------------------------------------------
template<int MODE>
__global__ void __launch_bounds__(256)
lgcn_gather(const float* __restrict__ cur,
            const float* __restrict__ user_emb,
            const float* __restrict__ item_emb,
            float*       __restrict__ nxt,
            float*       __restrict__ out)
{
    __shared__ int2 s_edges[8][32];
    const int wslot = threadIdx.x >> 5;
    const int lane  = threadIdx.x & 31;
    const int node  = blockIdx.x * 8 + wslot;
    if (node >= N_NODES) return;

    const int start = g_rowptr[node];
    const int end   = g_rowptr[node + 1];

    float2 acc = make_float2(0.f, 0.f);

    for (int base = start; base < end; base += 32) {
        int idx = base + lane;
        if (idx < end) s_edges[wslot][lane] = g_edges[idx];
        __syncwarp();
        const int n = min(32, end - base);
        #pragma unroll 8
        for (int j = 0; j < n; j++) {
            int2  cv = s_edges[wslot][j];
            float vj = __int_as_float(cv.y);
            const float2* src;
            if (MODE == 0) {
                src = (cv.x < NUM_USERS)
                    ? (const float2*)user_emb + (size_t)cv.x * (DIM / 2)
                    : (const float2*)item_emb + (size_t)(cv.x - NUM_USERS) * (DIM / 2);
            } else {
                src = (const float2*)cur + (size_t)cv.x * (DIM / 2);
            }
            float2 x = src[lane];
            acc.x += vj * x.x;
            acc.y += vj * x.y;
        }
        __syncwarp();
    }

    float2* o = (float2*)out + (size_t)node * (DIM / 2) + lane - lane; // base
    o = (float2*)(out + (size_t)node * DIM) ;

    if (MODE == 0) {
        const float2* e = (node < NUM_USERS)
            ? (const float2*)user_emb + (size_t)node * (DIM / 2)
            : (const float2*)item_emb + (size_t)(node - NUM_USERS) * (DIM / 2);
        float2 ev = e[lane];
        float2 r  = make_float2(ev.x + acc.x, ev.y + acc.y);
        o[lane] = r;
        ((float2*)(nxt + (size_t)node * DIM))[lane] = acc;
    } else if (MODE == 1) {
        float2 a = o[lane];
        a.x += acc.x; a.y += acc.y;
        o[lane] = a;
        ((float2*)(nxt + (size_t)node * DIM))[lane] = acc;
    } else {
        float2 a = o[lane];
        a.x = (a.x + acc.x) * 0.25f;
        a.y = (a.y + acc.y) * 0.25f;
        o[lane] = a;
    }
}

// -------------------------------------------------------------------------
// Launch: 7 kernels, graph-capturable, no sync, no alloc.
// -------------------------------------------------------------------------
extern "C" void kernel_launch(void* const* d_in, const int* in_sizes, int n_in,
                              void* d_out, int out_size)
{
    const float* user_emb  = (const float*)d_in[0];
    const float* item_emb  = (const float*)d_in[1];
    const float* edge_vals = (const float*)d_in[2];
    const int*   edge_row  = (const int*)d_in[3];
    const int*   edge_col  = (const int*)d_in[4];
    float* out = (float*)d_out;

    float *bufA, *bufB;
    cudaGetSymbolAddress((void**)&bufA, g_bufA);
    cudaGetSymbolAddress((void**)&bufB, g_bufB);

    const int zero_grid = (N_NODES + 255) / 256;
    const int e4_grid   = (NUM_EDGES / 4 + 255) / 256;
    const int gather_grid = (N_NODES + 7) / 8;   // 8 warps/block

    // Build CSR (re-done every replay: deterministic, no cached state).
    lgcn_zero_hist<<<zero_grid, 256>>>();
    lgcn_hist<<<e4_grid, 256>>>(edge_row);
    lgcn_scan<<<1, 1024>>>();
    lgcn_scatter<<<e4_grid, 256>>>(edge_vals, edge_row, edge_col);

    // 3 propagation layers, accumulation fused.
    lgcn_gather<0><<<gather_grid, 256>>>(nullptr, user_emb, item_emb, bufB, out);
    lgcn_gather<1><<<gather_grid, 256>>>(bufB,    user_emb, item_emb, bufA, out);
    lgcn_gather<2><<<gather_grid, 256>>>(bufA,    user_emb, item_emb, nullptr, out);
}